// round 12
// baseline (speedup 1.0000x reference)
#include <cuda_runtime.h>
#include <cuda_bf16.h>
#include <cuda_fp16.h>
#include <math.h>
#include <stdint.h>

typedef unsigned short u16;
typedef unsigned int   u32;
typedef unsigned long long u64;

#define BATCH 4
#define CIN   2048
#define NPIX  2304
#define DHID  256

// ---------------- scratch (static device globals; no allocations) ----------
__device__ u16 g_fL16[(size_t)BATCH*CIN*NPIX];   // features fp16 [B][C][N] (V)
__device__ u16 g_fR16[(size_t)BATCH*CIN*NPIX];
__device__ u16 g_fTLhi[(size_t)BATCH*NPIX*CIN];  // transposed [B][N][C] bf16 hi/lo
__device__ u16 g_fTLlo[(size_t)BATCH*NPIX*CIN];
__device__ u16 g_fTRhi[(size_t)BATCH*NPIX*CIN];
__device__ u16 g_fTRlo[(size_t)BATCH*NPIX*CIN];
__device__ u16 g_wqrhi[(size_t)2*DHID*CIN];      // wq||wr concat [512][2048] bf16 hi/lo
__device__ u16 g_wqrlo[(size_t)2*DHID*CIN];
__device__ float g_bqr[2*DHID];                  // bq||br
__device__ u16 g_QLhi[(size_t)BATCH*NPIX*DHID];
__device__ u16 g_QLlo[(size_t)BATCH*NPIX*DHID];
__device__ u16 g_KRhi[(size_t)BATCH*NPIX*DHID];
__device__ u16 g_KRlo[(size_t)BATCH*NPIX*DHID];
__device__ u16 g_QRhi[(size_t)BATCH*NPIX*DHID];
__device__ u16 g_QRlo[(size_t)BATCH*NPIX*DHID];
__device__ u16 g_KLhi[(size_t)BATCH*NPIX*DHID];
__device__ u16 g_KLlo[(size_t)BATCH*NPIX*DHID];
__device__ float g_S0[(size_t)BATCH*NPIX*NPIX];  // fp32 scores dir0
__device__ float g_S1[(size_t)BATCH*NPIX*NPIX];  // fp32 scores dir1
__device__ u16 g_A0[(size_t)BATCH*NPIX*NPIX];    // attn fp16 dir0
__device__ u16 g_A1[(size_t)BATCH*NPIX*NPIX];    // attn fp16 dir1

// ---------------- helpers ----------------------------------------------------
__device__ __forceinline__ u32 smem_u32(const void* p) {
    u32 a;
    asm("{ .reg .u64 t; cvta.to.shared.u64 t, %1; cvt.u32.u64 %0, t; }" : "=r"(a) : "l"(p));
    return a;
}
__device__ __forceinline__ void cp16(u32 dst, const void* src) {
    asm volatile("cp.async.cg.shared.global [%0], [%1], 16;" :: "r"(dst), "l"(src));
}
__device__ __forceinline__ void cp_commit() {
    asm volatile("cp.async.commit_group;" ::: "memory");
}
__device__ __forceinline__ void cp_wait1() {
    asm volatile("cp.async.wait_group 1;" ::: "memory");
}
__device__ __forceinline__ void ldsm_x4(u32& r0, u32& r1, u32& r2, u32& r3, u32 addr) {
    asm volatile("ldmatrix.sync.aligned.m8n8.x4.shared.b16 {%0,%1,%2,%3}, [%4];"
                 : "=r"(r0), "=r"(r1), "=r"(r2), "=r"(r3) : "r"(addr));
}
__device__ __forceinline__ void mma_bf16(float* d, const u32* a, u32 b0, u32 b1) {
    asm volatile(
        "mma.sync.aligned.m16n8k16.row.col.f32.bf16.bf16.f32 "
        "{%0,%1,%2,%3}, {%4,%5,%6,%7}, {%8,%9}, {%0,%1,%2,%3};"
        : "+f"(d[0]), "+f"(d[1]), "+f"(d[2]), "+f"(d[3])
        : "r"(a[0]), "r"(a[1]), "r"(a[2]), "r"(a[3]), "r"(b0), "r"(b1));
}
__device__ __forceinline__ void mma_f16(float* d, const u32* a, u32 b0, u32 b1) {
    asm volatile(
        "mma.sync.aligned.m16n8k16.row.col.f32.f16.f16.f32 "
        "{%0,%1,%2,%3}, {%4,%5,%6,%7}, {%8,%9}, {%0,%1,%2,%3};"
        : "+f"(d[0]), "+f"(d[1]), "+f"(d[2]), "+f"(d[3])
        : "r"(a[0]), "r"(a[1]), "r"(a[2]), "r"(a[3]), "r"(b0), "r"(b1));
}
__device__ __forceinline__ void split2(float v, u16& h, u16& l) {   // bf16 split
    __nv_bfloat16 hb = __float2bfloat16(v);
    float r = v - __bfloat162float(hb);
    __nv_bfloat16 lb = __float2bfloat16(r);
    h = *reinterpret_cast<u16*>(&hb);
    l = *reinterpret_cast<u16*>(&lb);
}
// swizzled byte offset inside a (rows x 32) 16-bit tile (row stride 64B)
__device__ __forceinline__ u32 swz(int row, int ch) {
    return (u32)(row * 64 + ((ch ^ ((row >> 1) & 3)) << 4));
}
// swizzled byte offset inside a (rows x 64) 16-bit tile (row stride 128B)
__device__ __forceinline__ u32 swz8(int row, int ch) {
    return (u32)(row * 128 + ((ch ^ (row & 7)) << 4));
}

// ============================================================================
// bf16 3-product GEMM core (CTA 128x128x32, 3 stages, 2 CTA/SM)
// Single-barrier pipeline: prefetch distance 2, refill stage (kt+2)%3 right
// after the top-of-loop barrier (that stage was consumed at kt-1; the barrier
// proves all warps finished reading it).
// ============================================================================
#define STAGES 3
#define STAGE_BYTES 32768
#define AHI_OFF 0
#define ALO_OFF 8192
#define BHI_OFF 16384
#define BLO_OFF 24576
#define GEMM_SMEM (STAGES * STAGE_BYTES)

#define BF16_MAINLOOP(ACC)                                                        \
    int s = 0;                                                                    \
    for (int kt = 0; kt < KT; ++kt) {                                             \
        cp_wait1();                                                               \
        __syncthreads();                                                          \
        const int sl = (s >= 1) ? s - 1 : 2;    /* (kt+2)%3 */                    \
        if (kt + 2 < KT) load_stage(kt + 2, sl);                                  \
        cp_commit();                                                              \
        const u32 base = sb + s * STAGE_BYTES;                                    \
        _Pragma("unroll")                                                         \
        for (int k16 = 0; k16 < 2; ++k16) {                                       \
            const int kc = k16 * 2 + kHi;                                         \
            u32 ah[2][4], al[2][4];                                               \
            _Pragma("unroll")                                                     \
            for (int mt = 0; mt < 2; ++mt) {                                      \
                const u32 off = swz(wm + mt * 16 + aRow, kc);                     \
                ldsm_x4(ah[mt][0], ah[mt][1], ah[mt][2], ah[mt][3], base + AHI_OFF + off); \
                ldsm_x4(al[mt][0], al[mt][1], al[mt][2], al[mt][3], base + ALO_OFF + off); \
            }                                                                     \
            _Pragma("unroll")                                                     \
            for (int nt4 = 0; nt4 < 4; ++nt4) {                                   \
                const u32 off = swz(wn + nt4 * 16 + bRow, kc);                    \
                u32 h0, h1, h2, h3, l0, l1, l2, l3;                               \
                ldsm_x4(h0, h1, h2, h3, base + BHI_OFF + off);                    \
                ldsm_x4(l0, l1, l2, l3, base + BLO_OFF + off);                    \
                _Pragma("unroll")                                                 \
                for (int mt = 0; mt < 2; ++mt) {                                  \
                    mma_bf16(ACC[mt][nt4*2],   ah[mt], h0, h2);                   \
                    mma_bf16(ACC[mt][nt4*2],   ah[mt], l0, l2);                   \
                    mma_bf16(ACC[mt][nt4*2],   al[mt], h0, h2);                   \
                    mma_bf16(ACC[mt][nt4*2+1], ah[mt], h1, h3);                   \
                    mma_bf16(ACC[mt][nt4*2+1], ah[mt], l1, l3);                   \
                    mma_bf16(ACC[mt][nt4*2+1], al[mt], h1, h3);                   \
                }                                                                 \
            }                                                                     \
        }                                                                         \
        s = (s == 2) ? 0 : s + 1;                                                 \
    }

// ---- merged projections (both features): grid z in [0,8): fz=z>>2, bz=z&3.
__global__ __launch_bounds__(256, 2)
void gemm_proj(const u16* __restrict__ AhiL, const u16* __restrict__ AloL,
               const u16* __restrict__ AhiR, const u16* __restrict__ AloR,
               const u16* __restrict__ Bhi, const u16* __restrict__ Blo,
               const float* __restrict__ bias,
               u16* __restrict__ QLhi, u16* __restrict__ QLlo,
               u16* __restrict__ KLhi, u16* __restrict__ KLlo,
               u16* __restrict__ QRhi, u16* __restrict__ QRlo,
               u16* __restrict__ KRhi, u16* __restrict__ KRlo)
{
    extern __shared__ char smem[];
    const u32 sb = smem_u32(smem);
    const int tid = threadIdx.x, lane = tid & 31, wid = tid >> 5;
    const int m0 = blockIdx.y * 128, n0 = blockIdx.x * 128;
    const int fz = blockIdx.z >> 2, bz = blockIdx.z & 3;
    const long long strideA = (long long)NPIX * CIN;

    const u16* Ahi = (fz ? AhiR : AhiL) + (long long)bz * strideA;
    const u16* Alo = (fz ? AloR : AloL) + (long long)bz * strideA;

    const int KT = CIN >> 5;  // 64

    const int r0l = tid >> 2,         c0l = tid & 3;
    const int r1l = (tid + 256) >> 2, c1l = tid & 3;
    const u32 o0 = swz(r0l, c0l), o1 = swz(r1l, c1l);

    auto load_stage = [&](int kt, int s) {
        const u32 base = sb + s * STAGE_BYTES;
        const int kc = kt * 32;
        {
            const long long ao = (long long)(m0 + r0l) * CIN + kc + c0l * 8;
            const long long bo = (long long)(n0 + r0l) * CIN + kc + c0l * 8;
            cp16(base + AHI_OFF + o0, Ahi + ao);
            cp16(base + ALO_OFF + o0, Alo + ao);
            cp16(base + BHI_OFF + o0, Bhi + bo);
            cp16(base + BLO_OFF + o0, Blo + bo);
        }
        {
            const long long ao = (long long)(m0 + r1l) * CIN + kc + c1l * 8;
            const long long bo = (long long)(n0 + r1l) * CIN + kc + c1l * 8;
            cp16(base + AHI_OFF + o1, Ahi + ao);
            cp16(base + ALO_OFF + o1, Alo + ao);
            cp16(base + BHI_OFF + o1, Bhi + bo);
            cp16(base + BLO_OFF + o1, Blo + bo);
        }
    };

    float acc[2][8][4];
#pragma unroll
    for (int i = 0; i < 2; ++i)
#pragma unroll
        for (int j = 0; j < 8; ++j)
#pragma unroll
            for (int q = 0; q < 4; ++q) acc[i][j][q] = 0.f;

    const int wm = (wid & 3) * 32;
    const int wn = (wid >> 2) * 64;
    const int aRow = (lane & 15);
    const int kHi  = (lane >> 4);
    const int bRow = (lane & 7) + ((lane >> 3) & 1) * 8;

    // 2-stage prologue
    load_stage(0, 0); cp_commit();
    load_stage(1, 1); cp_commit();

    BF16_MAINLOOP(acc)

    u16* Chi = (n0 >= 256) ? (fz ? KRhi : KLhi) : (fz ? QRhi : QLhi);
    u16* Clo = (n0 >= 256) ? (fz ? KRlo : KLlo) : (fz ? QRlo : QLlo);
    const long long qkStride = (long long)NPIX * DHID;
    const int tq = lane >> 2;
    const int tr = (lane & 3) * 2;
#pragma unroll
    for (int mt = 0; mt < 2; ++mt) {
#pragma unroll
        for (int nt = 0; nt < 8; ++nt) {
            const int m = m0 + wm + mt * 16 + tq;
            const int ng = n0 + wn + nt * 8 + tr;
            const int n = ng & 255;
            const float* a = acc[mt][nt];
            const long long b0 = (long long)bz * qkStride + (long long)m * DHID + n;
            const long long b1 = b0 + 8 * DHID;
            const float bv0 = bias[ng], bv1 = bias[ng + 1];
            u16 h0, l0, h1, l1;
            split2(a[0] + bv0, h0, l0); split2(a[1] + bv1, h1, l1);
            *reinterpret_cast<u32*>(Chi + b0) = (u32)h0 | ((u32)h1 << 16);
            *reinterpret_cast<u32*>(Clo + b0) = (u32)l0 | ((u32)l1 << 16);
            split2(a[2] + bv0, h0, l0); split2(a[3] + bv1, h1, l1);
            *reinterpret_cast<u32*>(Chi + b1) = (u32)h0 | ((u32)h1 << 16);
            *reinterpret_cast<u32*>(Clo + b1) = (u32)l0 | ((u32)l1 << 16);
        }
    }
}

// ---- merged scores (both directions): z in [0,8): dir=z>>2, bz=z&3.
__global__ __launch_bounds__(256, 2)
void gemm_qk(const u16* __restrict__ QLhi, const u16* __restrict__ QLlo,
             const u16* __restrict__ QRhi, const u16* __restrict__ QRlo,
             const u16* __restrict__ KRhi, const u16* __restrict__ KRlo,
             const u16* __restrict__ KLhi, const u16* __restrict__ KLlo,
             float* __restrict__ S0p, float* __restrict__ S1p)
{
    extern __shared__ char smem[];
    const u32 sb = smem_u32(smem);
    const int tid = threadIdx.x, lane = tid & 31, wid = tid >> 5;
    const int m0 = blockIdx.y * 128, n0 = blockIdx.x * 128;
    const int dir = blockIdx.z >> 2, bz = blockIdx.z & 3;
    const long long strideAB = (long long)NPIX * DHID;
    const long long strideC  = (long long)NPIX * NPIX;

    const u16* Ahi = (dir ? QRhi : QLhi) + (long long)bz * strideAB;
    const u16* Alo = (dir ? QRlo : QLlo) + (long long)bz * strideAB;
    const u16* Bhi = (dir ? KLhi : KRhi) + (long long)bz * strideAB;
    const u16* Blo = (dir ? KLlo : KRlo) + (long long)bz * strideAB;
    float* C = dir ? S1p : S0p;

    const int KT = DHID >> 5;  // 8

    const int r0l = tid >> 2,         c0l = tid & 3;
    const int r1l = (tid + 256) >> 2, c1l = tid & 3;
    const u32 o0 = swz(r0l, c0l), o1 = swz(r1l, c1l);

    auto load_stage = [&](int kt, int s) {
        const u32 base = sb + s * STAGE_BYTES;
        const int kc = kt * 32;
        {
            const long long ao = (long long)(m0 + r0l) * DHID + kc + c0l * 8;
            const long long bo = (long long)(n0 + r0l) * DHID + kc + c0l * 8;
            cp16(base + AHI_OFF + o0, Ahi + ao);
            cp16(base + ALO_OFF + o0, Alo + ao);
            cp16(base + BHI_OFF + o0, Bhi + bo);
            cp16(base + BLO_OFF + o0, Blo + bo);
        }
        {
            const long long ao = (long long)(m0 + r1l) * DHID + kc + c1l * 8;
            const long long bo = (long long)(n0 + r1l) * DHID + kc + c1l * 8;
            cp16(base + AHI_OFF + o1, Ahi + ao);
            cp16(base + ALO_OFF + o1, Alo + ao);
            cp16(base + BHI_OFF + o1, Bhi + bo);
            cp16(base + BLO_OFF + o1, Blo + bo);
        }
    };

    float acc[2][8][4];
#pragma unroll
    for (int i = 0; i < 2; ++i)
#pragma unroll
        for (int j = 0; j < 8; ++j)
#pragma unroll
            for (int q = 0; q < 4; ++q) acc[i][j][q] = 0.f;

    const int wm = (wid & 3) * 32;
    const int wn = (wid >> 2) * 64;
    const int aRow = (lane & 15);
    const int kHi  = (lane >> 4);
    const int bRow = (lane & 7) + ((lane >> 3) & 1) * 8;

    load_stage(0, 0); cp_commit();
    load_stage(1, 1); cp_commit();

    BF16_MAINLOOP(acc)

    const int tq = lane >> 2;
    const int tr = (lane & 3) * 2;
#pragma unroll
    for (int mt = 0; mt < 2; ++mt) {
#pragma unroll
        for (int nt = 0; nt < 8; ++nt) {
            const int m = m0 + wm + mt * 16 + tq;
            const int n = n0 + wn + nt * 8 + tr;
            const float* a = acc[mt][nt];
            const long long b0 = (long long)bz * strideC + (long long)m * NPIX + n;
            const long long b1 = b0 + 8 * NPIX;
            *reinterpret_cast<float2*>(C + b0) = make_float2(a[0], a[1]);
            *reinterpret_cast<float2*>(C + b1) = make_float2(a[2], a[3]);
        }
    }
}

// ============================================================================
// merged attn.V (both directions): fp16 single product, CTA 128x128x64,
// 3 stages, 2 CTA/SM, single-barrier pipeline. z in [0,8): dir=z>>2, bz=z&3.
// ============================================================================
#define AV_STAGES 3
#define AV_STG 32768
#define AV_A 0
#define AV_B 16384
#define AV_SMEM (AV_STAGES * AV_STG)

__global__ __launch_bounds__(256, 2)
void gemm_av(const u16* __restrict__ fR16p, const u16* __restrict__ fL16p,
             const u16* __restrict__ A0p, const u16* __restrict__ A1p,
             float* __restrict__ outLw, float* __restrict__ outRw)
{
    extern __shared__ char smem[];
    const u32 sb = smem_u32(smem);
    const int tid = threadIdx.x, lane = tid & 31, wid = tid >> 5;
    const int m0 = blockIdx.y * 128, n0 = blockIdx.x * 128;
    const int dir = blockIdx.z >> 2, bz = blockIdx.z & 3;
    const long long strideA = (long long)CIN * NPIX;
    const long long strideB = (long long)NPIX * NPIX;
    const long long strideC = 2LL * CIN * NPIX;

    const u16* A = (dir ? fL16p : fR16p) + (long long)bz * strideA;
    const u16* B = (dir ? A1p : A0p) + (long long)bz * strideB;
    float* C = dir ? outRw : outLw;

    const int KT = NPIX >> 6;  // 36

    auto load_stage = [&](int kt, int s) {
        const u32 base = sb + s * AV_STG;
        const int kc = kt * 64;
#pragma unroll
        for (int i = 0; i < 4; ++i) {
            const int idx = tid + i * 256;
            const int row = idx >> 3, ch = idx & 7;
            const u32 off = swz8(row, ch);
            cp16(base + AV_A + off, A + (long long)(m0 + row) * NPIX + kc + ch * 8);
            cp16(base + AV_B + off, B + (long long)(n0 + row) * NPIX + kc + ch * 8);
        }
    };

    float acc[2][8][4];
#pragma unroll
    for (int i = 0; i < 2; ++i)
#pragma unroll
        for (int j = 0; j < 8; ++j)
#pragma unroll
            for (int q = 0; q < 4; ++q) acc[i][j][q] = 0.f;

    const int wm = (wid & 3) * 32;
    const int wn = (wid >> 2) * 64;
    const int aRow = (lane & 15);
    const int kHi  = (lane >> 4);
    const int bRow = (lane & 7) + ((lane >> 3) & 1) * 8;

    load_stage(0, 0); cp_commit();
    load_stage(1, 1); cp_commit();

    int s = 0;
    for (int kt = 0; kt < KT; ++kt) {
        cp_wait1();
        __syncthreads();
        const int sl = (s >= 1) ? s - 1 : 2;    // (kt+2)%3
        if (kt + 2 < KT) load_stage(kt + 2, sl);
        cp_commit();
        const u32 base = sb + s * AV_STG;

#pragma unroll
        for (int k16 = 0; k16 < 4; ++k16) {
            const int kc = k16 * 2 + kHi;
            u32 ah[2][4];
#pragma unroll
            for (int mt = 0; mt < 2; ++mt) {
                const u32 off = swz8(wm + mt * 16 + aRow, kc);
                ldsm_x4(ah[mt][0], ah[mt][1], ah[mt][2], ah[mt][3], base + AV_A + off);
            }
            u32 bb[8][2];
#pragma unroll
            for (int nt4 = 0; nt4 < 4; ++nt4) {
                const u32 off = swz8(wn + nt4 * 16 + bRow, kc);
                u32 x0, x1, x2, x3;
                ldsm_x4(x0, x1, x2, x3, base + AV_B + off);
                bb[nt4*2][0] = x0; bb[nt4*2][1] = x2;
                bb[nt4*2+1][0] = x1; bb[nt4*2+1][1] = x3;
            }
#pragma unroll
            for (int mt = 0; mt < 2; ++mt)
#pragma unroll
                for (int nt = 0; nt < 8; ++nt)
                    mma_f16(acc[mt][nt], ah[mt], bb[nt][0], bb[nt][1]);
        }
        s = (s == 2) ? 0 : s + 1;
    }

    const int tq = lane >> 2;
    const int tr = (lane & 3) * 2;
#pragma unroll
    for (int mt = 0; mt < 2; ++mt) {
#pragma unroll
        for (int nt = 0; nt < 8; ++nt) {
            const int m = m0 + wm + mt * 16 + tq;
            const int n = n0 + wn + nt * 8 + tr;
            const float* a = acc[mt][nt];
            const long long b0 = (long long)bz * strideC + (long long)m * NPIX + n;
            const long long b1 = b0 + 8 * NPIX;
            *reinterpret_cast<float2*>(C + b0) = make_float2(a[0], a[1]);
            *reinterpret_cast<float2*>(C + b1) = make_float2(a[2], a[3]);
        }
    }
}

// ---------------- fused feature prep (both sides in one launch) --------------
__global__ __launch_bounds__(256)
void prep_features(const float* __restrict__ L, const float* __restrict__ R,
                   float* __restrict__ outL, float* __restrict__ outR,
                   u16* __restrict__ fL16p, u16* __restrict__ fR16p,
                   u16* __restrict__ hiL, u16* __restrict__ loL,
                   u16* __restrict__ hiR, u16* __restrict__ loR)
{
    __shared__ float tile[32][33];
    const int side = blockIdx.z >> 2, b = blockIdx.z & 3;
    const int n0 = blockIdx.x * 32;
    const int c0 = blockIdx.y * 32;
    const int tx = threadIdx.x, ty = threadIdx.y;  // 32 x 8

    const float* X = side ? R : L;
    float* outDst = side ? outR : outL;
    u16* f16 = side ? fR16p : fL16p;
    u16* hi = side ? hiR : hiL;
    u16* lo = side ? loR : loL;

    const float* src = X + ((long long)b * CIN + c0) * NPIX + n0;
#pragma unroll
    for (int r = 0; r < 32; r += 8) {
        const float v = src[(long long)(ty + r) * NPIX + tx];
        tile[ty + r][tx] = v;
        const long long cIdx = c0 + ty + r;
        outDst[((long long)b * 2 * CIN + cIdx) * NPIX + n0 + tx] = v;
        __half h = __float2half_rn(v);
        f16[((long long)b * CIN + cIdx) * NPIX + n0 + tx] = *reinterpret_cast<u16*>(&h);
    }
    __syncthreads();
#pragma unroll
    for (int r = 0; r < 32; r += 8) {
        float v = tile[tx][ty + r];
        u16 h, l; split2(v, h, l);
        long long o = ((long long)b * NPIX + n0 + ty + r) * CIN + c0 + tx;
        hi[o] = h; lo[o] = l;
    }
}

// merged weight prep: splits wq and wr into the concat arrays, plus bias concat.
__global__ __launch_bounds__(256)
void prep_weights(const float4* __restrict__ wq4, const float4* __restrict__ wr4,
                  uint2* __restrict__ hi, uint2* __restrict__ lo,
                  const float* __restrict__ bq, const float* __restrict__ br,
                  float* __restrict__ bdst)
{
    const long long nW4 = (long long)DHID * CIN / 4;   // per-weight uint2 count
    long long i = (long long)blockIdx.x * 256 + threadIdx.x;
    if (i < 2 * nW4) {
        const int second = i >= nW4;
        const long long j = second ? i - nW4 : i;
        float4 v = second ? wr4[j] : wq4[j];
        u16 h0,l0,h1,l1,h2,l2,h3,l3;
        split2(v.x,h0,l0); split2(v.y,h1,l1); split2(v.z,h2,l2); split2(v.w,h3,l3);
        hi[i] = make_uint2((u32)h0 | ((u32)h1 << 16), (u32)h2 | ((u32)h3 << 16));
        lo[i] = make_uint2((u32)l0 | ((u32)l1 << 16), (u32)l2 | ((u32)l3 << 16));
    }
    if (blockIdx.x == 0) {
        int t = threadIdx.x;
        bdst[t] = bq[t];
        bdst[t + 256] = br[t];
    }
}

// merged row softmax (both directions) fp32 -> attn fp16
__global__ __launch_bounds__(256)
void softmax_h(const float* __restrict__ S0p, const float* __restrict__ S1p,
               u16* __restrict__ A0p, u16* __restrict__ A1p)
{
    const int PER = NPIX / 256;  // 9
    const int total = BATCH * NPIX;
    const int dir = blockIdx.x >= total;
    const long long rb = (long long)(dir ? blockIdx.x - total : blockIdx.x) * NPIX;
    const float* p = (dir ? S1p : S0p) + rb;
    u16* A = (dir ? A1p : A0p);
    const int tid = threadIdx.x;

    float v[PER];
    float mx = -INFINITY;
#pragma unroll
    for (int i = 0; i < PER; ++i) { v[i] = p[tid + i*256]; mx = fmaxf(mx, v[i]); }

    __shared__ float red[8];
#pragma unroll
    for (int o = 16; o; o >>= 1) mx = fmaxf(mx, __shfl_xor_sync(0xffffffffu, mx, o));
    if ((tid & 31) == 0) red[tid >> 5] = mx;
    __syncthreads();
    mx = red[0];
#pragma unroll
    for (int i = 1; i < 8; ++i) mx = fmaxf(mx, red[i]);
    __syncthreads();

    float s = 0.f;
#pragma unroll
    for (int i = 0; i < PER; ++i) { v[i] = __expf(v[i] - mx); s += v[i]; }
#pragma unroll
    for (int o = 16; o; o >>= 1) s += __shfl_xor_sync(0xffffffffu, s, o);
    if ((tid & 31) == 0) red[tid >> 5] = s;
    __syncthreads();
    s = red[0];
#pragma unroll
    for (int i = 1; i < 8; ++i) s += red[i];

    const float inv = 1.f / s;
#pragma unroll
    for (int i = 0; i < PER; ++i) {
        __half h = __float2half_rn(v[i] * inv);
        A[rb + tid + i*256] = *reinterpret_cast<u16*>(&h);
    }
}

// ---------------- host --------------------------------------------------------
extern "C" void kernel_launch(void* const* d_in, const int* in_sizes, int n_in,
                              void* d_out, int out_size)
{
    const float* left  = (const float*)d_in[0];
    const float* right = (const float*)d_in[1];
    const float* wq    = (const float*)d_in[2];
    const float* bq    = (const float*)d_in[3];
    const float* wr    = (const float*)d_in[4];
    const float* br    = (const float*)d_in[5];
    float* out = (float*)d_out;

    void *fL16, *fR16, *fTLhi, *fTLlo, *fTRhi, *fTRlo;
    void *wqrhi, *wqrlo, *bqr;
    void *QLhi, *QLlo, *KRhi, *KRlo, *QRhi, *QRlo, *KLhi, *KLlo;
    void *S0, *S1, *A0, *A1;
    cudaGetSymbolAddress(&fL16, g_fL16);   cudaGetSymbolAddress(&fR16, g_fR16);
    cudaGetSymbolAddress(&fTLhi, g_fTLhi); cudaGetSymbolAddress(&fTLlo, g_fTLlo);
    cudaGetSymbolAddress(&fTRhi, g_fTRhi); cudaGetSymbolAddress(&fTRlo, g_fTRlo);
    cudaGetSymbolAddress(&wqrhi, g_wqrhi); cudaGetSymbolAddress(&wqrlo, g_wqrlo);
    cudaGetSymbolAddress(&bqr, g_bqr);
    cudaGetSymbolAddress(&QLhi, g_QLhi);   cudaGetSymbolAddress(&QLlo, g_QLlo);
    cudaGetSymbolAddress(&KRhi, g_KRhi);   cudaGetSymbolAddress(&KRlo, g_KRlo);
    cudaGetSymbolAddress(&QRhi, g_QRhi);   cudaGetSymbolAddress(&QRlo, g_QRlo);
    cudaGetSymbolAddress(&KLhi, g_KLhi);   cudaGetSymbolAddress(&KLlo, g_KLlo);
    cudaGetSymbolAddress(&S0, g_S0);       cudaGetSymbolAddress(&S1, g_S1);
    cudaGetSymbolAddress(&A0, g_A0);       cudaGetSymbolAddress(&A1, g_A1);

    cudaFuncSetAttribute(gemm_proj, cudaFuncAttributeMaxDynamicSharedMemorySize, GEMM_SMEM);
    cudaFuncSetAttribute(gemm_qk,   cudaFuncAttributeMaxDynamicSharedMemorySize, GEMM_SMEM);
    cudaFuncSetAttribute(gemm_av,   cudaFuncAttributeMaxDynamicSharedMemorySize, AV_SMEM);

    const long long outStride = 2LL * CIN * NPIX;
    float* outL = out;
    float* outR = out + (long long)BATCH * outStride;

    // ---- prep: weights + bias in one launch, fused feature prep ----
    {
        const long long nW4 = (long long)DHID * CIN / 4;
        prep_weights<<<(unsigned)((2 * nW4 + 255) / 256), 256>>>(
            (const float4*)wq, (const float4*)wr,
            (uint2*)wqrhi, (uint2*)wqrlo, bq, br, (float*)bqr);
        dim3 tg(NPIX / 32, CIN / 32, 2 * BATCH);
        prep_features<<<tg, dim3(32, 8)>>>(left, right, outL, outR,
            (u16*)fL16, (u16*)fR16,
            (u16*)fTLhi, (u16*)fTLlo, (u16*)fTRhi, (u16*)fTRlo);
    }

    // ---- merged projections (both features, one launch) ----
    {
        dim3 grid(2 * DHID / 128, NPIX / 128, 2 * BATCH);  // 4 x 18 x 8
        gemm_proj<<<grid, 256, GEMM_SMEM>>>(
            (const u16*)fTLhi, (const u16*)fTLlo, (const u16*)fTRhi, (const u16*)fTRlo,
            (const u16*)wqrhi, (const u16*)wqrlo, (const float*)bqr,
            (u16*)QLhi, (u16*)QLlo, (u16*)KLhi, (u16*)KLlo,
            (u16*)QRhi, (u16*)QRlo, (u16*)KRhi, (u16*)KRlo);
    }

    // ---- merged scores (both directions, one launch) ----
    {
        dim3 grid(NPIX / 128, NPIX / 128, 2 * BATCH);  // 18 x 18 x 8
        gemm_qk<<<grid, 256, GEMM_SMEM>>>(
            (const u16*)QLhi, (const u16*)QLlo, (const u16*)QRhi, (const u16*)QRlo,
            (const u16*)KRhi, (const u16*)KRlo, (const u16*)KLhi, (const u16*)KLlo,
            (float*)S0, (float*)S1);
    }

    // ---- merged softmax ----
    softmax_h<<<2 * BATCH * NPIX, 256>>>((const float*)S0, (const float*)S1,
                                         (u16*)A0, (u16*)A1);

    // ---- merged attn.V (both directions, one launch) ----
    {
        dim3 grid(NPIX / 128, CIN / 128, 2 * BATCH);   // 18 x 16 x 8
        gemm_av<<<grid, 256, AV_SMEM>>>(
            (const u16*)fR16, (const u16*)fL16, (const u16*)A0, (const u16*)A1,
            outL + (long long)CIN * NPIX, outR + (long long)CIN * NPIX);
    }
}

// round 13
// speedup vs baseline: 1.0311x; 1.0311x over previous
#include <cuda_runtime.h>
#include <cuda_bf16.h>
#include <cuda_fp16.h>
#include <math.h>
#include <stdint.h>

typedef unsigned short u16;
typedef unsigned int   u32;
typedef unsigned long long u64;

#define BATCH 4
#define CIN   2048
#define NPIX  2304
#define DHID  256

// ---------------- scratch (static device globals; no allocations) ----------
__device__ u16 g_fL16[(size_t)BATCH*CIN*NPIX];   // features fp16 [B][C][N] (V)
__device__ u16 g_fR16[(size_t)BATCH*CIN*NPIX];
__device__ u16 g_fTLhi[(size_t)BATCH*NPIX*CIN];  // transposed [B][N][C] bf16 hi/lo
__device__ u16 g_fTLlo[(size_t)BATCH*NPIX*CIN];
__device__ u16 g_fTRhi[(size_t)BATCH*NPIX*CIN];
__device__ u16 g_fTRlo[(size_t)BATCH*NPIX*CIN];
__device__ u16 g_wqrhi[(size_t)2*DHID*CIN];      // wq||wr concat [512][2048] bf16 hi/lo
__device__ u16 g_wqrlo[(size_t)2*DHID*CIN];
__device__ float g_bqr[2*DHID];                  // bq||br
__device__ u16 g_QLhi[(size_t)BATCH*NPIX*DHID];
__device__ u16 g_QLlo[(size_t)BATCH*NPIX*DHID];
__device__ u16 g_KRhi[(size_t)BATCH*NPIX*DHID];
__device__ u16 g_KRlo[(size_t)BATCH*NPIX*DHID];
__device__ u16 g_QRhi[(size_t)BATCH*NPIX*DHID];
__device__ u16 g_QRlo[(size_t)BATCH*NPIX*DHID];
__device__ u16 g_KLhi[(size_t)BATCH*NPIX*DHID];
__device__ u16 g_KLlo[(size_t)BATCH*NPIX*DHID];
__device__ float g_S0[(size_t)BATCH*NPIX*NPIX];  // fp32 scores dir0
__device__ float g_S1[(size_t)BATCH*NPIX*NPIX];  // fp32 scores dir1
__device__ u16 g_A0[(size_t)BATCH*NPIX*NPIX];    // attn fp16 dir0
__device__ u16 g_A1[(size_t)BATCH*NPIX*NPIX];    // attn fp16 dir1

// ---------------- helpers ----------------------------------------------------
__device__ __forceinline__ u32 smem_u32(const void* p) {
    u32 a;
    asm("{ .reg .u64 t; cvta.to.shared.u64 t, %1; cvt.u32.u64 %0, t; }" : "=r"(a) : "l"(p));
    return a;
}
__device__ __forceinline__ void cp16(u32 dst, const void* src) {
    asm volatile("cp.async.cg.shared.global [%0], [%1], 16;" :: "r"(dst), "l"(src));
}
__device__ __forceinline__ void cp_commit() {
    asm volatile("cp.async.commit_group;" ::: "memory");
}
__device__ __forceinline__ void cp_wait1() {
    asm volatile("cp.async.wait_group 1;" ::: "memory");
}
__device__ __forceinline__ void ldsm_x4(u32& r0, u32& r1, u32& r2, u32& r3, u32 addr) {
    asm volatile("ldmatrix.sync.aligned.m8n8.x4.shared.b16 {%0,%1,%2,%3}, [%4];"
                 : "=r"(r0), "=r"(r1), "=r"(r2), "=r"(r3) : "r"(addr));
}
__device__ __forceinline__ void mma_bf16(float* d, const u32* a, u32 b0, u32 b1) {
    asm volatile(
        "mma.sync.aligned.m16n8k16.row.col.f32.bf16.bf16.f32 "
        "{%0,%1,%2,%3}, {%4,%5,%6,%7}, {%8,%9}, {%0,%1,%2,%3};"
        : "+f"(d[0]), "+f"(d[1]), "+f"(d[2]), "+f"(d[3])
        : "r"(a[0]), "r"(a[1]), "r"(a[2]), "r"(a[3]), "r"(b0), "r"(b1));
}
__device__ __forceinline__ void mma_f16(float* d, const u32* a, u32 b0, u32 b1) {
    asm volatile(
        "mma.sync.aligned.m16n8k16.row.col.f32.f16.f16.f32 "
        "{%0,%1,%2,%3}, {%4,%5,%6,%7}, {%8,%9}, {%0,%1,%2,%3};"
        : "+f"(d[0]), "+f"(d[1]), "+f"(d[2]), "+f"(d[3])
        : "r"(a[0]), "r"(a[1]), "r"(a[2]), "r"(a[3]), "r"(b0), "r"(b1));
}
__device__ __forceinline__ void split2(float v, u16& h, u16& l) {   // bf16 split
    __nv_bfloat16 hb = __float2bfloat16(v);
    float r = v - __bfloat162float(hb);
    __nv_bfloat16 lb = __float2bfloat16(r);
    h = *reinterpret_cast<u16*>(&hb);
    l = *reinterpret_cast<u16*>(&lb);
}
// swizzled byte offset inside a (rows x 32) 16-bit tile (row stride 64B)
__device__ __forceinline__ u32 swz(int row, int ch) {
    return (u32)(row * 64 + ((ch ^ ((row >> 1) & 3)) << 4));
}
// swizzled byte offset inside a (rows x 64) 16-bit tile (row stride 128B)
__device__ __forceinline__ u32 swz8(int row, int ch) {
    return (u32)(row * 128 + ((ch ^ (row & 7)) << 4));
}

// ============================================================================
// bf16 3-product GEMM core (CTA 128x128x32, 3 stages, 2 CTA/SM)
// Single barrier per kt; the stage refill is injected BETWEEN the two k16
// compute blocks so cp.async issue overhead hides under the mma stream.
// ============================================================================
#define STAGES 3
#define STAGE_BYTES 32768
#define AHI_OFF 0
#define ALO_OFF 8192
#define BHI_OFF 16384
#define BLO_OFF 24576
#define GEMM_SMEM (STAGES * STAGE_BYTES)

#define BF16_K16_BLOCK(ACC, K16)                                                  \
    {                                                                             \
        const int kc = (K16) * 2 + kHi;                                           \
        u32 ah[2][4], al[2][4];                                                   \
        _Pragma("unroll")                                                         \
        for (int mt = 0; mt < 2; ++mt) {                                          \
            const u32 off = swz(wm + mt * 16 + aRow, kc);                         \
            ldsm_x4(ah[mt][0], ah[mt][1], ah[mt][2], ah[mt][3], base + AHI_OFF + off); \
            ldsm_x4(al[mt][0], al[mt][1], al[mt][2], al[mt][3], base + ALO_OFF + off); \
        }                                                                         \
        _Pragma("unroll")                                                         \
        for (int nt4 = 0; nt4 < 4; ++nt4) {                                       \
            const u32 off = swz(wn + nt4 * 16 + bRow, kc);                        \
            u32 h0, h1, h2, h3, l0, l1, l2, l3;                                   \
            ldsm_x4(h0, h1, h2, h3, base + BHI_OFF + off);                        \
            ldsm_x4(l0, l1, l2, l3, base + BLO_OFF + off);                        \
            _Pragma("unroll")                                                     \
            for (int mt = 0; mt < 2; ++mt) {                                      \
                mma_bf16(ACC[mt][nt4*2],   ah[mt], h0, h2);                       \
                mma_bf16(ACC[mt][nt4*2],   ah[mt], l0, l2);                       \
                mma_bf16(ACC[mt][nt4*2],   al[mt], h0, h2);                       \
                mma_bf16(ACC[mt][nt4*2+1], ah[mt], h1, h3);                       \
                mma_bf16(ACC[mt][nt4*2+1], ah[mt], l1, l3);                       \
                mma_bf16(ACC[mt][nt4*2+1], al[mt], h1, h3);                       \
            }                                                                     \
        }                                                                         \
    }

#define BF16_MAINLOOP(ACC)                                                        \
    int s = 0;                                                                    \
    for (int kt = 0; kt < KT; ++kt) {                                             \
        cp_wait1();                                                               \
        __syncthreads();                                                          \
        const u32 base = sb + s * STAGE_BYTES;                                    \
        BF16_K16_BLOCK(ACC, 0)                                                    \
        {   /* refill the stage consumed at kt-1, hidden under mma stream */      \
            const int sl = (s >= 1) ? s - 1 : 2;  /* (kt+2)%3 */                  \
            if (kt + 2 < KT) load_stage(kt + 2, sl);                              \
            cp_commit();                                                          \
        }                                                                         \
        BF16_K16_BLOCK(ACC, 1)                                                    \
        s = (s == 2) ? 0 : s + 1;                                                 \
    }

// ---- merged projections (both features): grid z in [0,8): fz=z>>2, bz=z&3.
__global__ __launch_bounds__(256, 2)
void gemm_proj(const u16* __restrict__ AhiL, const u16* __restrict__ AloL,
               const u16* __restrict__ AhiR, const u16* __restrict__ AloR,
               const u16* __restrict__ Bhi, const u16* __restrict__ Blo,
               const float* __restrict__ bias,
               u16* __restrict__ QLhi, u16* __restrict__ QLlo,
               u16* __restrict__ KLhi, u16* __restrict__ KLlo,
               u16* __restrict__ QRhi, u16* __restrict__ QRlo,
               u16* __restrict__ KRhi, u16* __restrict__ KRlo)
{
    extern __shared__ char smem[];
    const u32 sb = smem_u32(smem);
    const int tid = threadIdx.x, lane = tid & 31, wid = tid >> 5;
    const int m0 = blockIdx.y * 128, n0 = blockIdx.x * 128;
    const int fz = blockIdx.z >> 2, bz = blockIdx.z & 3;
    const long long strideA = (long long)NPIX * CIN;

    const u16* Ahi = (fz ? AhiR : AhiL) + (long long)bz * strideA;
    const u16* Alo = (fz ? AloR : AloL) + (long long)bz * strideA;

    const int KT = CIN >> 5;  // 64

    const int r0l = tid >> 2,         c0l = tid & 3;
    const int r1l = (tid + 256) >> 2, c1l = tid & 3;
    const u32 o0 = swz(r0l, c0l), o1 = swz(r1l, c1l);

    auto load_stage = [&](int kt, int s) {
        const u32 base = sb + s * STAGE_BYTES;
        const int kc = kt * 32;
        {
            const long long ao = (long long)(m0 + r0l) * CIN + kc + c0l * 8;
            const long long bo = (long long)(n0 + r0l) * CIN + kc + c0l * 8;
            cp16(base + AHI_OFF + o0, Ahi + ao);
            cp16(base + ALO_OFF + o0, Alo + ao);
            cp16(base + BHI_OFF + o0, Bhi + bo);
            cp16(base + BLO_OFF + o0, Blo + bo);
        }
        {
            const long long ao = (long long)(m0 + r1l) * CIN + kc + c1l * 8;
            const long long bo = (long long)(n0 + r1l) * CIN + kc + c1l * 8;
            cp16(base + AHI_OFF + o1, Ahi + ao);
            cp16(base + ALO_OFF + o1, Alo + ao);
            cp16(base + BHI_OFF + o1, Bhi + bo);
            cp16(base + BLO_OFF + o1, Blo + bo);
        }
    };

    float acc[2][8][4];
#pragma unroll
    for (int i = 0; i < 2; ++i)
#pragma unroll
        for (int j = 0; j < 8; ++j)
#pragma unroll
            for (int q = 0; q < 4; ++q) acc[i][j][q] = 0.f;

    const int wm = (wid & 3) * 32;
    const int wn = (wid >> 2) * 64;
    const int aRow = (lane & 15);
    const int kHi  = (lane >> 4);
    const int bRow = (lane & 7) + ((lane >> 3) & 1) * 8;

    load_stage(0, 0); cp_commit();
    load_stage(1, 1); cp_commit();

    BF16_MAINLOOP(acc)

    u16* Chi = (n0 >= 256) ? (fz ? KRhi : KLhi) : (fz ? QRhi : QLhi);
    u16* Clo = (n0 >= 256) ? (fz ? KRlo : KLlo) : (fz ? QRlo : QLlo);
    const long long qkStride = (long long)NPIX * DHID;
    const int tq = lane >> 2;
    const int tr = (lane & 3) * 2;
#pragma unroll
    for (int mt = 0; mt < 2; ++mt) {
#pragma unroll
        for (int nt = 0; nt < 8; ++nt) {
            const int m = m0 + wm + mt * 16 + tq;
            const int ng = n0 + wn + nt * 8 + tr;
            const int n = ng & 255;
            const float* a = acc[mt][nt];
            const long long b0 = (long long)bz * qkStride + (long long)m * DHID + n;
            const long long b1 = b0 + 8 * DHID;
            const float bv0 = bias[ng], bv1 = bias[ng + 1];
            u16 h0, l0, h1, l1;
            split2(a[0] + bv0, h0, l0); split2(a[1] + bv1, h1, l1);
            *reinterpret_cast<u32*>(Chi + b0) = (u32)h0 | ((u32)h1 << 16);
            *reinterpret_cast<u32*>(Clo + b0) = (u32)l0 | ((u32)l1 << 16);
            split2(a[2] + bv0, h0, l0); split2(a[3] + bv1, h1, l1);
            *reinterpret_cast<u32*>(Chi + b1) = (u32)h0 | ((u32)h1 << 16);
            *reinterpret_cast<u32*>(Clo + b1) = (u32)l0 | ((u32)l1 << 16);
        }
    }
}

// ---- merged scores (both directions): z in [0,8): dir=z>>2, bz=z&3.
__global__ __launch_bounds__(256, 2)
void gemm_qk(const u16* __restrict__ QLhi, const u16* __restrict__ QLlo,
             const u16* __restrict__ QRhi, const u16* __restrict__ QRlo,
             const u16* __restrict__ KRhi, const u16* __restrict__ KRlo,
             const u16* __restrict__ KLhi, const u16* __restrict__ KLlo,
             float* __restrict__ S0p, float* __restrict__ S1p)
{
    extern __shared__ char smem[];
    const u32 sb = smem_u32(smem);
    const int tid = threadIdx.x, lane = tid & 31, wid = tid >> 5;
    const int m0 = blockIdx.y * 128, n0 = blockIdx.x * 128;
    const int dir = blockIdx.z >> 2, bz = blockIdx.z & 3;
    const long long strideAB = (long long)NPIX * DHID;
    const long long strideC  = (long long)NPIX * NPIX;

    const u16* Ahi = (dir ? QRhi : QLhi) + (long long)bz * strideAB;
    const u16* Alo = (dir ? QRlo : QLlo) + (long long)bz * strideAB;
    const u16* Bhi = (dir ? KLhi : KRhi) + (long long)bz * strideAB;
    const u16* Blo = (dir ? KLlo : KRlo) + (long long)bz * strideAB;
    float* C = dir ? S1p : S0p;

    const int KT = DHID >> 5;  // 8

    const int r0l = tid >> 2,         c0l = tid & 3;
    const int r1l = (tid + 256) >> 2, c1l = tid & 3;
    const u32 o0 = swz(r0l, c0l), o1 = swz(r1l, c1l);

    auto load_stage = [&](int kt, int s) {
        const u32 base = sb + s * STAGE_BYTES;
        const int kc = kt * 32;
        {
            const long long ao = (long long)(m0 + r0l) * DHID + kc + c0l * 8;
            const long long bo = (long long)(n0 + r0l) * DHID + kc + c0l * 8;
            cp16(base + AHI_OFF + o0, Ahi + ao);
            cp16(base + ALO_OFF + o0, Alo + ao);
            cp16(base + BHI_OFF + o0, Bhi + bo);
            cp16(base + BLO_OFF + o0, Blo + bo);
        }
        {
            const long long ao = (long long)(m0 + r1l) * DHID + kc + c1l * 8;
            const long long bo = (long long)(n0 + r1l) * DHID + kc + c1l * 8;
            cp16(base + AHI_OFF + o1, Ahi + ao);
            cp16(base + ALO_OFF + o1, Alo + ao);
            cp16(base + BHI_OFF + o1, Bhi + bo);
            cp16(base + BLO_OFF + o1, Blo + bo);
        }
    };

    float acc[2][8][4];
#pragma unroll
    for (int i = 0; i < 2; ++i)
#pragma unroll
        for (int j = 0; j < 8; ++j)
#pragma unroll
            for (int q = 0; q < 4; ++q) acc[i][j][q] = 0.f;

    const int wm = (wid & 3) * 32;
    const int wn = (wid >> 2) * 64;
    const int aRow = (lane & 15);
    const int kHi  = (lane >> 4);
    const int bRow = (lane & 7) + ((lane >> 3) & 1) * 8;

    load_stage(0, 0); cp_commit();
    load_stage(1, 1); cp_commit();

    BF16_MAINLOOP(acc)

    const int tq = lane >> 2;
    const int tr = (lane & 3) * 2;
#pragma unroll
    for (int mt = 0; mt < 2; ++mt) {
#pragma unroll
        for (int nt = 0; nt < 8; ++nt) {
            const int m = m0 + wm + mt * 16 + tq;
            const int n = n0 + wn + nt * 8 + tr;
            const float* a = acc[mt][nt];
            const long long b0 = (long long)bz * strideC + (long long)m * NPIX + n;
            const long long b1 = b0 + 8 * NPIX;
            *reinterpret_cast<float2*>(C + b0) = make_float2(a[0], a[1]);
            *reinterpret_cast<float2*>(C + b1) = make_float2(a[2], a[3]);
        }
    }
}

// ============================================================================
// merged attn.V (both directions): fp16 single product, CTA 128x128x64,
// 3 stages, 2 CTA/SM, single barrier, mid-stream refill.
// ============================================================================
#define AV_STAGES 3
#define AV_STG 32768
#define AV_A 0
#define AV_B 16384
#define AV_SMEM (AV_STAGES * AV_STG)

__global__ __launch_bounds__(256, 2)
void gemm_av(const u16* __restrict__ fR16p, const u16* __restrict__ fL16p,
             const u16* __restrict__ A0p, const u16* __restrict__ A1p,
             float* __restrict__ outLw, float* __restrict__ outRw)
{
    extern __shared__ char smem[];
    const u32 sb = smem_u32(smem);
    const int tid = threadIdx.x, lane = tid & 31, wid = tid >> 5;
    const int m0 = blockIdx.y * 128, n0 = blockIdx.x * 128;
    const int dir = blockIdx.z >> 2, bz = blockIdx.z & 3;
    const long long strideA = (long long)CIN * NPIX;
    const long long strideB = (long long)NPIX * NPIX;
    const long long strideC = 2LL * CIN * NPIX;

    const u16* A = (dir ? fL16p : fR16p) + (long long)bz * strideA;
    const u16* B = (dir ? A1p : A0p) + (long long)bz * strideB;
    float* C = dir ? outRw : outLw;

    const int KT = NPIX >> 6;  // 36

    auto load_stage = [&](int kt, int s) {
        const u32 base = sb + s * AV_STG;
        const int kc = kt * 64;
#pragma unroll
        for (int i = 0; i < 4; ++i) {
            const int idx = tid + i * 256;
            const int row = idx >> 3, ch = idx & 7;
            const u32 off = swz8(row, ch);
            cp16(base + AV_A + off, A + (long long)(m0 + row) * NPIX + kc + ch * 8);
            cp16(base + AV_B + off, B + (long long)(n0 + row) * NPIX + kc + ch * 8);
        }
    };

    float acc[2][8][4];
#pragma unroll
    for (int i = 0; i < 2; ++i)
#pragma unroll
        for (int j = 0; j < 8; ++j)
#pragma unroll
            for (int q = 0; q < 4; ++q) acc[i][j][q] = 0.f;

    const int wm = (wid & 3) * 32;
    const int wn = (wid >> 2) * 64;
    const int aRow = (lane & 15);
    const int kHi  = (lane >> 4);
    const int bRow = (lane & 7) + ((lane >> 3) & 1) * 8;

    load_stage(0, 0); cp_commit();
    load_stage(1, 1); cp_commit();

    int s = 0;
    for (int kt = 0; kt < KT; ++kt) {
        cp_wait1();
        __syncthreads();
        const u32 base = sb + s * AV_STG;

#pragma unroll
        for (int k16 = 0; k16 < 4; ++k16) {
            const int kc = k16 * 2 + kHi;
            u32 ah[2][4];
#pragma unroll
            for (int mt = 0; mt < 2; ++mt) {
                const u32 off = swz8(wm + mt * 16 + aRow, kc);
                ldsm_x4(ah[mt][0], ah[mt][1], ah[mt][2], ah[mt][3], base + AV_A + off);
            }
            u32 bb[8][2];
#pragma unroll
            for (int nt4 = 0; nt4 < 4; ++nt4) {
                const u32 off = swz8(wn + nt4 * 16 + bRow, kc);
                u32 x0, x1, x2, x3;
                ldsm_x4(x0, x1, x2, x3, base + AV_B + off);
                bb[nt4*2][0] = x0; bb[nt4*2][1] = x2;
                bb[nt4*2+1][0] = x1; bb[nt4*2+1][1] = x3;
            }
#pragma unroll
            for (int mt = 0; mt < 2; ++mt)
#pragma unroll
                for (int nt = 0; nt < 8; ++nt)
                    mma_f16(acc[mt][nt], ah[mt], bb[nt][0], bb[nt][1]);

            if (k16 == 0) {   // mid-stream refill, hidden under mma blocks
                const int sl = (s >= 1) ? s - 1 : 2;  // (kt+2)%3
                if (kt + 2 < KT) load_stage(kt + 2, sl);
                cp_commit();
            }
        }
        s = (s == 2) ? 0 : s + 1;
    }

    const int tq = lane >> 2;
    const int tr = (lane & 3) * 2;
#pragma unroll
    for (int mt = 0; mt < 2; ++mt) {
#pragma unroll
        for (int nt = 0; nt < 8; ++nt) {
            const int m = m0 + wm + mt * 16 + tq;
            const int n = n0 + wn + nt * 8 + tr;
            const float* a = acc[mt][nt];
            const long long b0 = (long long)bz * strideC + (long long)m * NPIX + n;
            const long long b1 = b0 + 8 * NPIX;
            *reinterpret_cast<float2*>(C + b0) = make_float2(a[0], a[1]);
            *reinterpret_cast<float2*>(C + b1) = make_float2(a[2], a[3]);
        }
    }
}

// ---------------- fused feature prep (both sides in one launch) --------------
__global__ __launch_bounds__(256)
void prep_features(const float* __restrict__ L, const float* __restrict__ R,
                   float* __restrict__ outL, float* __restrict__ outR,
                   u16* __restrict__ fL16p, u16* __restrict__ fR16p,
                   u16* __restrict__ hiL, u16* __restrict__ loL,
                   u16* __restrict__ hiR, u16* __restrict__ loR)
{
    __shared__ float tile[32][33];
    const int side = blockIdx.z >> 2, b = blockIdx.z & 3;
    const int n0 = blockIdx.x * 32;
    const int c0 = blockIdx.y * 32;
    const int tx = threadIdx.x, ty = threadIdx.y;  // 32 x 8

    const float* X = side ? R : L;
    float* outDst = side ? outR : outL;
    u16* f16 = side ? fR16p : fL16p;
    u16* hi = side ? hiR : hiL;
    u16* lo = side ? loR : loL;

    const float* src = X + ((long long)b * CIN + c0) * NPIX + n0;
#pragma unroll
    for (int r = 0; r < 32; r += 8) {
        const float v = src[(long long)(ty + r) * NPIX + tx];
        tile[ty + r][tx] = v;
        const long long cIdx = c0 + ty + r;
        outDst[((long long)b * 2 * CIN + cIdx) * NPIX + n0 + tx] = v;
        __half h = __float2half_rn(v);
        f16[((long long)b * CIN + cIdx) * NPIX + n0 + tx] = *reinterpret_cast<u16*>(&h);
    }
    __syncthreads();
#pragma unroll
    for (int r = 0; r < 32; r += 8) {
        float v = tile[tx][ty + r];
        u16 h, l; split2(v, h, l);
        long long o = ((long long)b * NPIX + n0 + ty + r) * CIN + c0 + tx;
        hi[o] = h; lo[o] = l;
    }
}

// merged weight prep: splits wq and wr into the concat arrays, plus bias concat.
__global__ __launch_bounds__(256)
void prep_weights(const float4* __restrict__ wq4, const float4* __restrict__ wr4,
                  uint2* __restrict__ hi, uint2* __restrict__ lo,
                  const float* __restrict__ bq, const float* __restrict__ br,
                  float* __restrict__ bdst)
{
    const long long nW4 = (long long)DHID * CIN / 4;   // per-weight uint2 count
    long long i = (long long)blockIdx.x * 256 + threadIdx.x;
    if (i < 2 * nW4) {
        const int second = i >= nW4;
        const long long j = second ? i - nW4 : i;
        float4 v = second ? wr4[j] : wq4[j];
        u16 h0,l0,h1,l1,h2,l2,h3,l3;
        split2(v.x,h0,l0); split2(v.y,h1,l1); split2(v.z,h2,l2); split2(v.w,h3,l3);
        hi[i] = make_uint2((u32)h0 | ((u32)h1 << 16), (u32)h2 | ((u32)h3 << 16));
        lo[i] = make_uint2((u32)l0 | ((u32)l1 << 16), (u32)l2 | ((u32)l3 << 16));
    }
    if (blockIdx.x == 0) {
        int t = threadIdx.x;
        bdst[t] = bq[t];
        bdst[t + 256] = br[t];
    }
}

// merged row softmax (both directions) fp32 -> attn fp16
__global__ __launch_bounds__(256)
void softmax_h(const float* __restrict__ S0p, const float* __restrict__ S1p,
               u16* __restrict__ A0p, u16* __restrict__ A1p)
{
    const int PER = NPIX / 256;  // 9
    const int total = BATCH * NPIX;
    const int dir = blockIdx.x >= total;
    const long long rb = (long long)(dir ? blockIdx.x - total : blockIdx.x) * NPIX;
    const float* p = (dir ? S1p : S0p) + rb;
    u16* A = (dir ? A1p : A0p);
    const int tid = threadIdx.x;

    float v[PER];
    float mx = -INFINITY;
#pragma unroll
    for (int i = 0; i < PER; ++i) { v[i] = p[tid + i*256]; mx = fmaxf(mx, v[i]); }

    __shared__ float red[8];
#pragma unroll
    for (int o = 16; o; o >>= 1) mx = fmaxf(mx, __shfl_xor_sync(0xffffffffu, mx, o));
    if ((tid & 31) == 0) red[tid >> 5] = mx;
    __syncthreads();
    mx = red[0];
#pragma unroll
    for (int i = 1; i < 8; ++i) mx = fmaxf(mx, red[i]);
    __syncthreads();

    float s = 0.f;
#pragma unroll
    for (int i = 0; i < PER; ++i) { v[i] = __expf(v[i] - mx); s += v[i]; }
#pragma unroll
    for (int o = 16; o; o >>= 1) s += __shfl_xor_sync(0xffffffffu, s, o);
    if ((tid & 31) == 0) red[tid >> 5] = s;
    __syncthreads();
    s = red[0];
#pragma unroll
    for (int i = 1; i < 8; ++i) s += red[i];

    const float inv = 1.f / s;
#pragma unroll
    for (int i = 0; i < PER; ++i) {
        __half h = __float2half_rn(v[i] * inv);
        A[rb + tid + i*256] = *reinterpret_cast<u16*>(&h);
    }
}

// ---------------- host --------------------------------------------------------
extern "C" void kernel_launch(void* const* d_in, const int* in_sizes, int n_in,
                              void* d_out, int out_size)
{
    const float* left  = (const float*)d_in[0];
    const float* right = (const float*)d_in[1];
    const float* wq    = (const float*)d_in[2];
    const float* bq    = (const float*)d_in[3];
    const float* wr    = (const float*)d_in[4];
    const float* br    = (const float*)d_in[5];
    float* out = (float*)d_out;

    void *fL16, *fR16, *fTLhi, *fTLlo, *fTRhi, *fTRlo;
    void *wqrhi, *wqrlo, *bqr;
    void *QLhi, *QLlo, *KRhi, *KRlo, *QRhi, *QRlo, *KLhi, *KLlo;
    void *S0, *S1, *A0, *A1;
    cudaGetSymbolAddress(&fL16, g_fL16);   cudaGetSymbolAddress(&fR16, g_fR16);
    cudaGetSymbolAddress(&fTLhi, g_fTLhi); cudaGetSymbolAddress(&fTLlo, g_fTLlo);
    cudaGetSymbolAddress(&fTRhi, g_fTRhi); cudaGetSymbolAddress(&fTRlo, g_fTRlo);
    cudaGetSymbolAddress(&wqrhi, g_wqrhi); cudaGetSymbolAddress(&wqrlo, g_wqrlo);
    cudaGetSymbolAddress(&bqr, g_bqr);
    cudaGetSymbolAddress(&QLhi, g_QLhi);   cudaGetSymbolAddress(&QLlo, g_QLlo);
    cudaGetSymbolAddress(&KRhi, g_KRhi);   cudaGetSymbolAddress(&KRlo, g_KRlo);
    cudaGetSymbolAddress(&QRhi, g_QRhi);   cudaGetSymbolAddress(&QRlo, g_QRlo);
    cudaGetSymbolAddress(&KLhi, g_KLhi);   cudaGetSymbolAddress(&KLlo, g_KLlo);
    cudaGetSymbolAddress(&S0, g_S0);       cudaGetSymbolAddress(&S1, g_S1);
    cudaGetSymbolAddress(&A0, g_A0);       cudaGetSymbolAddress(&A1, g_A1);

    cudaFuncSetAttribute(gemm_proj, cudaFuncAttributeMaxDynamicSharedMemorySize, GEMM_SMEM);
    cudaFuncSetAttribute(gemm_qk,   cudaFuncAttributeMaxDynamicSharedMemorySize, GEMM_SMEM);
    cudaFuncSetAttribute(gemm_av,   cudaFuncAttributeMaxDynamicSharedMemorySize, AV_SMEM);

    const long long outStride = 2LL * CIN * NPIX;
    float* outL = out;
    float* outR = out + (long long)BATCH * outStride;

    // ---- prep: weights + bias in one launch, fused feature prep ----
    {
        const long long nW4 = (long long)DHID * CIN / 4;
        prep_weights<<<(unsigned)((2 * nW4 + 255) / 256), 256>>>(
            (const float4*)wq, (const float4*)wr,
            (uint2*)wqrhi, (uint2*)wqrlo, bq, br, (float*)bqr);
        dim3 tg(NPIX / 32, CIN / 32, 2 * BATCH);
        prep_features<<<tg, dim3(32, 8)>>>(left, right, outL, outR,
            (u16*)fL16, (u16*)fR16,
            (u16*)fTLhi, (u16*)fTLlo, (u16*)fTRhi, (u16*)fTRlo);
    }

    // ---- merged projections (both features, one launch) ----
    {
        dim3 grid(2 * DHID / 128, NPIX / 128, 2 * BATCH);  // 4 x 18 x 8
        gemm_proj<<<grid, 256, GEMM_SMEM>>>(
            (const u16*)fTLhi, (const u16*)fTLlo, (const u16*)fTRhi, (const u16*)fTRlo,
            (const u16*)wqrhi, (const u16*)wqrlo, (const float*)bqr,
            (u16*)QLhi, (u16*)QLlo, (u16*)KLhi, (u16*)KLlo,
            (u16*)QRhi, (u16*)QRlo, (u16*)KRhi, (u16*)KRlo);
    }

    // ---- merged scores (both directions, one launch) ----
    {
        dim3 grid(NPIX / 128, NPIX / 128, 2 * BATCH);  // 18 x 18 x 8
        gemm_qk<<<grid, 256, GEMM_SMEM>>>(
            (const u16*)QLhi, (const u16*)QLlo, (const u16*)QRhi, (const u16*)QRlo,
            (const u16*)KRhi, (const u16*)KRlo, (const u16*)KLhi, (const u16*)KLlo,
            (float*)S0, (float*)S1);
    }

    // ---- merged softmax ----
    softmax_h<<<2 * BATCH * NPIX, 256>>>((const float*)S0, (const float*)S1,
                                         (u16*)A0, (u16*)A1);

    // ---- merged attn.V (both directions, one launch) ----
    {
        dim3 grid(NPIX / 128, CIN / 128, 2 * BATCH);   // 18 x 16 x 8
        gemm_av<<<grid, 256, AV_SMEM>>>(
            (const u16*)fR16, (const u16*)fL16, (const u16*)A0, (const u16*)A1,
            outL + (long long)CIN * NPIX, outR + (long long)CIN * NPIX);
    }
}

// round 14
// speedup vs baseline: 1.0323x; 1.0011x over previous
#include <cuda_runtime.h>
#include <cuda_bf16.h>
#include <cuda_fp16.h>
#include <math.h>
#include <stdint.h>

typedef unsigned short u16;
typedef unsigned int   u32;
typedef unsigned long long u64;

#define BATCH 4
#define CIN   2048
#define NPIX  2304
#define DHID  256

// ---------------- scratch (static device globals; no allocations) ----------
__device__ u16 g_fL16[(size_t)BATCH*CIN*NPIX];   // features fp16 [B][C][N] (V)
__device__ u16 g_fR16[(size_t)BATCH*CIN*NPIX];
__device__ u16 g_fTLhi[(size_t)BATCH*NPIX*CIN];  // transposed [B][N][C] bf16 hi/lo
__device__ u16 g_fTLlo[(size_t)BATCH*NPIX*CIN];
__device__ u16 g_fTRhi[(size_t)BATCH*NPIX*CIN];
__device__ u16 g_fTRlo[(size_t)BATCH*NPIX*CIN];
__device__ u16 g_wqrhi[(size_t)2*DHID*CIN];      // wq||wr concat [512][2048] bf16 hi/lo
__device__ u16 g_wqrlo[(size_t)2*DHID*CIN];
__device__ float g_bqr[2*DHID];                  // bq||br
__device__ u16 g_QLhi[(size_t)BATCH*NPIX*DHID];
__device__ u16 g_QLlo[(size_t)BATCH*NPIX*DHID];
__device__ u16 g_KRhi[(size_t)BATCH*NPIX*DHID];
__device__ u16 g_KRlo[(size_t)BATCH*NPIX*DHID];
__device__ u16 g_QRhi[(size_t)BATCH*NPIX*DHID];
__device__ u16 g_QRlo[(size_t)BATCH*NPIX*DHID];
__device__ u16 g_KLhi[(size_t)BATCH*NPIX*DHID];
__device__ u16 g_KLlo[(size_t)BATCH*NPIX*DHID];
__device__ float g_S0[(size_t)BATCH*NPIX*NPIX];  // fp32 scores dir0
__device__ float g_S1[(size_t)BATCH*NPIX*NPIX];  // fp32 scores dir1
__device__ u16 g_A0[(size_t)BATCH*NPIX*NPIX];    // attn fp16 dir0
__device__ u16 g_A1[(size_t)BATCH*NPIX*NPIX];    // attn fp16 dir1

// ---------------- helpers ----------------------------------------------------
__device__ __forceinline__ u32 smem_u32(const void* p) {
    u32 a;
    asm("{ .reg .u64 t; cvta.to.shared.u64 t, %1; cvt.u32.u64 %0, t; }" : "=r"(a) : "l"(p));
    return a;
}
__device__ __forceinline__ void cp16(u32 dst, const void* src) {
    asm volatile("cp.async.cg.shared.global [%0], [%1], 16;" :: "r"(dst), "l"(src));
}
__device__ __forceinline__ void cp_commit() {
    asm volatile("cp.async.commit_group;" ::: "memory");
}
__device__ __forceinline__ void cp_wait1() {
    asm volatile("cp.async.wait_group 1;" ::: "memory");
}
__device__ __forceinline__ void ldsm_x4(u32& r0, u32& r1, u32& r2, u32& r3, u32 addr) {
    asm volatile("ldmatrix.sync.aligned.m8n8.x4.shared.b16 {%0,%1,%2,%3}, [%4];"
                 : "=r"(r0), "=r"(r1), "=r"(r2), "=r"(r3) : "r"(addr));
}
__device__ __forceinline__ void mma_bf16(float* d, const u32* a, u32 b0, u32 b1) {
    asm volatile(
        "mma.sync.aligned.m16n8k16.row.col.f32.bf16.bf16.f32 "
        "{%0,%1,%2,%3}, {%4,%5,%6,%7}, {%8,%9}, {%0,%1,%2,%3};"
        : "+f"(d[0]), "+f"(d[1]), "+f"(d[2]), "+f"(d[3])
        : "r"(a[0]), "r"(a[1]), "r"(a[2]), "r"(a[3]), "r"(b0), "r"(b1));
}
__device__ __forceinline__ void mma_f16(float* d, const u32* a, u32 b0, u32 b1) {
    asm volatile(
        "mma.sync.aligned.m16n8k16.row.col.f32.f16.f16.f32 "
        "{%0,%1,%2,%3}, {%4,%5,%6,%7}, {%8,%9}, {%0,%1,%2,%3};"
        : "+f"(d[0]), "+f"(d[1]), "+f"(d[2]), "+f"(d[3])
        : "r"(a[0]), "r"(a[1]), "r"(a[2]), "r"(a[3]), "r"(b0), "r"(b1));
}
__device__ __forceinline__ void split2(float v, u16& h, u16& l) {   // bf16 split
    __nv_bfloat16 hb = __float2bfloat16(v);
    float r = v - __bfloat162float(hb);
    __nv_bfloat16 lb = __float2bfloat16(r);
    h = *reinterpret_cast<u16*>(&hb);
    l = *reinterpret_cast<u16*>(&lb);
}
// swizzled byte offset inside a (rows x 32) 16-bit tile (row stride 64B)
__device__ __forceinline__ u32 swz(int row, int ch) {
    return (u32)(row * 64 + ((ch ^ ((row >> 1) & 3)) << 4));
}
// swizzled byte offset inside a (rows x 64) 16-bit tile (row stride 128B)
__device__ __forceinline__ u32 swz8(int row, int ch) {
    return (u32)(row * 128 + ((ch ^ (row & 7)) << 4));
}

// ============================================================================
// bf16 3-product GEMM core (CTA 128x128x32, 3 stages, 2 CTA/SM)
// Single barrier per kt, mid-stream refill. The k16 block emits the three
// product passes SEPARATELY (hi*hi x16, hi*lo x16, lo*hi x16) so each acc
// register is reused only every 16 MMAs — breaks HMMA RAW serialization.
// Per-accumulator operation order is unchanged (bitwise-identical results).
// ============================================================================
#define STAGES 3
#define STAGE_BYTES 32768
#define AHI_OFF 0
#define ALO_OFF 8192
#define BHI_OFF 16384
#define BLO_OFF 24576
#define GEMM_SMEM (STAGES * STAGE_BYTES)

#define BF16_K16_BLOCK(ACC, K16)                                                  \
    {                                                                             \
        const int kc = (K16) * 2 + kHi;                                           \
        u32 ah[2][4], al[2][4];                                                   \
        _Pragma("unroll")                                                         \
        for (int mt = 0; mt < 2; ++mt) {                                          \
            const u32 off = swz(wm + mt * 16 + aRow, kc);                         \
            ldsm_x4(ah[mt][0], ah[mt][1], ah[mt][2], ah[mt][3], base + AHI_OFF + off); \
            ldsm_x4(al[mt][0], al[mt][1], al[mt][2], al[mt][3], base + ALO_OFF + off); \
        }                                                                         \
        u32 bh[8][2], bl[8][2];                                                   \
        _Pragma("unroll")                                                         \
        for (int nt4 = 0; nt4 < 4; ++nt4) {                                       \
            const u32 off = swz(wn + nt4 * 16 + bRow, kc);                        \
            u32 x0, x1, x2, x3;                                                   \
            ldsm_x4(x0, x1, x2, x3, base + BHI_OFF + off);                        \
            bh[nt4*2][0] = x0; bh[nt4*2][1] = x2;                                 \
            bh[nt4*2+1][0] = x1; bh[nt4*2+1][1] = x3;                             \
            ldsm_x4(x0, x1, x2, x3, base + BLO_OFF + off);                        \
            bl[nt4*2][0] = x0; bl[nt4*2][1] = x2;                                 \
            bl[nt4*2+1][0] = x1; bl[nt4*2+1][1] = x3;                             \
        }                                                                         \
        _Pragma("unroll")                                                         \
        for (int mt = 0; mt < 2; ++mt)                                            \
            _Pragma("unroll")                                                     \
            for (int nt = 0; nt < 8; ++nt)                                        \
                mma_bf16(ACC[mt][nt], ah[mt], bh[nt][0], bh[nt][1]);              \
        _Pragma("unroll")                                                         \
        for (int mt = 0; mt < 2; ++mt)                                            \
            _Pragma("unroll")                                                     \
            for (int nt = 0; nt < 8; ++nt)                                        \
                mma_bf16(ACC[mt][nt], ah[mt], bl[nt][0], bl[nt][1]);              \
        _Pragma("unroll")                                                         \
        for (int mt = 0; mt < 2; ++mt)                                            \
            _Pragma("unroll")                                                     \
            for (int nt = 0; nt < 8; ++nt)                                        \
                mma_bf16(ACC[mt][nt], al[mt], bh[nt][0], bh[nt][1]);              \
    }

#define BF16_MAINLOOP(ACC)                                                        \
    int s = 0;                                                                    \
    for (int kt = 0; kt < KT; ++kt) {                                             \
        cp_wait1();                                                               \
        __syncthreads();                                                          \
        const u32 base = sb + s * STAGE_BYTES;                                    \
        BF16_K16_BLOCK(ACC, 0)                                                    \
        {   /* refill the stage consumed at kt-1, hidden under mma stream */      \
            const int sl = (s >= 1) ? s - 1 : 2;  /* (kt+2)%3 */                  \
            if (kt + 2 < KT) load_stage(kt + 2, sl);                              \
            cp_commit();                                                          \
        }                                                                         \
        BF16_K16_BLOCK(ACC, 1)                                                    \
        s = (s == 2) ? 0 : s + 1;                                                 \
    }

// ---- merged projections (both features): grid z in [0,8): fz=z>>2, bz=z&3.
__global__ __launch_bounds__(256, 2)
void gemm_proj(const u16* __restrict__ AhiL, const u16* __restrict__ AloL,
               const u16* __restrict__ AhiR, const u16* __restrict__ AloR,
               const u16* __restrict__ Bhi, const u16* __restrict__ Blo,
               const float* __restrict__ bias,
               u16* __restrict__ QLhi, u16* __restrict__ QLlo,
               u16* __restrict__ KLhi, u16* __restrict__ KLlo,
               u16* __restrict__ QRhi, u16* __restrict__ QRlo,
               u16* __restrict__ KRhi, u16* __restrict__ KRlo)
{
    extern __shared__ char smem[];
    const u32 sb = smem_u32(smem);
    const int tid = threadIdx.x, lane = tid & 31, wid = tid >> 5;
    const int m0 = blockIdx.y * 128, n0 = blockIdx.x * 128;
    const int fz = blockIdx.z >> 2, bz = blockIdx.z & 3;
    const long long strideA = (long long)NPIX * CIN;

    const u16* Ahi = (fz ? AhiR : AhiL) + (long long)bz * strideA;
    const u16* Alo = (fz ? AloR : AloL) + (long long)bz * strideA;

    const int KT = CIN >> 5;  // 64

    const int r0l = tid >> 2,         c0l = tid & 3;
    const int r1l = (tid + 256) >> 2, c1l = tid & 3;
    const u32 o0 = swz(r0l, c0l), o1 = swz(r1l, c1l);

    auto load_stage = [&](int kt, int s) {
        const u32 base = sb + s * STAGE_BYTES;
        const int kc = kt * 32;
        {
            const long long ao = (long long)(m0 + r0l) * CIN + kc + c0l * 8;
            const long long bo = (long long)(n0 + r0l) * CIN + kc + c0l * 8;
            cp16(base + AHI_OFF + o0, Ahi + ao);
            cp16(base + ALO_OFF + o0, Alo + ao);
            cp16(base + BHI_OFF + o0, Bhi + bo);
            cp16(base + BLO_OFF + o0, Blo + bo);
        }
        {
            const long long ao = (long long)(m0 + r1l) * CIN + kc + c1l * 8;
            const long long bo = (long long)(n0 + r1l) * CIN + kc + c1l * 8;
            cp16(base + AHI_OFF + o1, Ahi + ao);
            cp16(base + ALO_OFF + o1, Alo + ao);
            cp16(base + BHI_OFF + o1, Bhi + bo);
            cp16(base + BLO_OFF + o1, Blo + bo);
        }
    };

    float acc[2][8][4];
#pragma unroll
    for (int i = 0; i < 2; ++i)
#pragma unroll
        for (int j = 0; j < 8; ++j)
#pragma unroll
            for (int q = 0; q < 4; ++q) acc[i][j][q] = 0.f;

    const int wm = (wid & 3) * 32;
    const int wn = (wid >> 2) * 64;
    const int aRow = (lane & 15);
    const int kHi  = (lane >> 4);
    const int bRow = (lane & 7) + ((lane >> 3) & 1) * 8;

    load_stage(0, 0); cp_commit();
    load_stage(1, 1); cp_commit();

    BF16_MAINLOOP(acc)

    u16* Chi = (n0 >= 256) ? (fz ? KRhi : KLhi) : (fz ? QRhi : QLhi);
    u16* Clo = (n0 >= 256) ? (fz ? KRlo : KLlo) : (fz ? QRlo : QLlo);
    const long long qkStride = (long long)NPIX * DHID;
    const int tq = lane >> 2;
    const int tr = (lane & 3) * 2;
#pragma unroll
    for (int mt = 0; mt < 2; ++mt) {
#pragma unroll
        for (int nt = 0; nt < 8; ++nt) {
            const int m = m0 + wm + mt * 16 + tq;
            const int ng = n0 + wn + nt * 8 + tr;
            const int n = ng & 255;
            const float* a = acc[mt][nt];
            const long long b0 = (long long)bz * qkStride + (long long)m * DHID + n;
            const long long b1 = b0 + 8 * DHID;
            const float bv0 = bias[ng], bv1 = bias[ng + 1];
            u16 h0, l0, h1, l1;
            split2(a[0] + bv0, h0, l0); split2(a[1] + bv1, h1, l1);
            *reinterpret_cast<u32*>(Chi + b0) = (u32)h0 | ((u32)h1 << 16);
            *reinterpret_cast<u32*>(Clo + b0) = (u32)l0 | ((u32)l1 << 16);
            split2(a[2] + bv0, h0, l0); split2(a[3] + bv1, h1, l1);
            *reinterpret_cast<u32*>(Chi + b1) = (u32)h0 | ((u32)h1 << 16);
            *reinterpret_cast<u32*>(Clo + b1) = (u32)l0 | ((u32)l1 << 16);
        }
    }
}

// ---- merged scores (both directions): z in [0,8): dir=z>>2, bz=z&3.
__global__ __launch_bounds__(256, 2)
void gemm_qk(const u16* __restrict__ QLhi, const u16* __restrict__ QLlo,
             const u16* __restrict__ QRhi, const u16* __restrict__ QRlo,
             const u16* __restrict__ KRhi, const u16* __restrict__ KRlo,
             const u16* __restrict__ KLhi, const u16* __restrict__ KLlo,
             float* __restrict__ S0p, float* __restrict__ S1p)
{
    extern __shared__ char smem[];
    const u32 sb = smem_u32(smem);
    const int tid = threadIdx.x, lane = tid & 31, wid = tid >> 5;
    const int m0 = blockIdx.y * 128, n0 = blockIdx.x * 128;
    const int dir = blockIdx.z >> 2, bz = blockIdx.z & 3;
    const long long strideAB = (long long)NPIX * DHID;
    const long long strideC  = (long long)NPIX * NPIX;

    const u16* Ahi = (dir ? QRhi : QLhi) + (long long)bz * strideAB;
    const u16* Alo = (dir ? QRlo : QLlo) + (long long)bz * strideAB;
    const u16* Bhi = (dir ? KLhi : KRhi) + (long long)bz * strideAB;
    const u16* Blo = (dir ? KLlo : KRlo) + (long long)bz * strideAB;
    float* C = dir ? S1p : S0p;

    const int KT = DHID >> 5;  // 8

    const int r0l = tid >> 2,         c0l = tid & 3;
    const int r1l = (tid + 256) >> 2, c1l = tid & 3;
    const u32 o0 = swz(r0l, c0l), o1 = swz(r1l, c1l);

    auto load_stage = [&](int kt, int s) {
        const u32 base = sb + s * STAGE_BYTES;
        const int kc = kt * 32;
        {
            const long long ao = (long long)(m0 + r0l) * DHID + kc + c0l * 8;
            const long long bo = (long long)(n0 + r0l) * DHID + kc + c0l * 8;
            cp16(base + AHI_OFF + o0, Ahi + ao);
            cp16(base + ALO_OFF + o0, Alo + ao);
            cp16(base + BHI_OFF + o0, Bhi + bo);
            cp16(base + BLO_OFF + o0, Blo + bo);
        }
        {
            const long long ao = (long long)(m0 + r1l) * DHID + kc + c1l * 8;
            const long long bo = (long long)(n0 + r1l) * DHID + kc + c1l * 8;
            cp16(base + AHI_OFF + o1, Ahi + ao);
            cp16(base + ALO_OFF + o1, Alo + ao);
            cp16(base + BHI_OFF + o1, Bhi + bo);
            cp16(base + BLO_OFF + o1, Blo + bo);
        }
    };

    float acc[2][8][4];
#pragma unroll
    for (int i = 0; i < 2; ++i)
#pragma unroll
        for (int j = 0; j < 8; ++j)
#pragma unroll
            for (int q = 0; q < 4; ++q) acc[i][j][q] = 0.f;

    const int wm = (wid & 3) * 32;
    const int wn = (wid >> 2) * 64;
    const int aRow = (lane & 15);
    const int kHi  = (lane >> 4);
    const int bRow = (lane & 7) + ((lane >> 3) & 1) * 8;

    load_stage(0, 0); cp_commit();
    load_stage(1, 1); cp_commit();

    BF16_MAINLOOP(acc)

    const int tq = lane >> 2;
    const int tr = (lane & 3) * 2;
#pragma unroll
    for (int mt = 0; mt < 2; ++mt) {
#pragma unroll
        for (int nt = 0; nt < 8; ++nt) {
            const int m = m0 + wm + mt * 16 + tq;
            const int n = n0 + wn + nt * 8 + tr;
            const float* a = acc[mt][nt];
            const long long b0 = (long long)bz * strideC + (long long)m * NPIX + n;
            const long long b1 = b0 + 8 * NPIX;
            *reinterpret_cast<float2*>(C + b0) = make_float2(a[0], a[1]);
            *reinterpret_cast<float2*>(C + b1) = make_float2(a[2], a[3]);
        }
    }
}

// ============================================================================
// merged attn.V (both directions): fp16 single product, CTA 128x128x64,
// 3 stages, 2 CTA/SM, single barrier, mid-stream refill.
// ============================================================================
#define AV_STAGES 3
#define AV_STG 32768
#define AV_A 0
#define AV_B 16384
#define AV_SMEM (AV_STAGES * AV_STG)

__global__ __launch_bounds__(256, 2)
void gemm_av(const u16* __restrict__ fR16p, const u16* __restrict__ fL16p,
             const u16* __restrict__ A0p, const u16* __restrict__ A1p,
             float* __restrict__ outLw, float* __restrict__ outRw)
{
    extern __shared__ char smem[];
    const u32 sb = smem_u32(smem);
    const int tid = threadIdx.x, lane = tid & 31, wid = tid >> 5;
    const int m0 = blockIdx.y * 128, n0 = blockIdx.x * 128;
    const int dir = blockIdx.z >> 2, bz = blockIdx.z & 3;
    const long long strideA = (long long)CIN * NPIX;
    const long long strideB = (long long)NPIX * NPIX;
    const long long strideC = 2LL * CIN * NPIX;

    const u16* A = (dir ? fL16p : fR16p) + (long long)bz * strideA;
    const u16* B = (dir ? A1p : A0p) + (long long)bz * strideB;
    float* C = dir ? outRw : outLw;

    const int KT = NPIX >> 6;  // 36

    auto load_stage = [&](int kt, int s) {
        const u32 base = sb + s * AV_STG;
        const int kc = kt * 64;
#pragma unroll
        for (int i = 0; i < 4; ++i) {
            const int idx = tid + i * 256;
            const int row = idx >> 3, ch = idx & 7;
            const u32 off = swz8(row, ch);
            cp16(base + AV_A + off, A + (long long)(m0 + row) * NPIX + kc + ch * 8);
            cp16(base + AV_B + off, B + (long long)(n0 + row) * NPIX + kc + ch * 8);
        }
    };

    float acc[2][8][4];
#pragma unroll
    for (int i = 0; i < 2; ++i)
#pragma unroll
        for (int j = 0; j < 8; ++j)
#pragma unroll
            for (int q = 0; q < 4; ++q) acc[i][j][q] = 0.f;

    const int wm = (wid & 3) * 32;
    const int wn = (wid >> 2) * 64;
    const int aRow = (lane & 15);
    const int kHi  = (lane >> 4);
    const int bRow = (lane & 7) + ((lane >> 3) & 1) * 8;

    load_stage(0, 0); cp_commit();
    load_stage(1, 1); cp_commit();

    int s = 0;
    for (int kt = 0; kt < KT; ++kt) {
        cp_wait1();
        __syncthreads();
        const u32 base = sb + s * AV_STG;

#pragma unroll
        for (int k16 = 0; k16 < 4; ++k16) {
            const int kc = k16 * 2 + kHi;
            u32 ah[2][4];
#pragma unroll
            for (int mt = 0; mt < 2; ++mt) {
                const u32 off = swz8(wm + mt * 16 + aRow, kc);
                ldsm_x4(ah[mt][0], ah[mt][1], ah[mt][2], ah[mt][3], base + AV_A + off);
            }
            u32 bb[8][2];
#pragma unroll
            for (int nt4 = 0; nt4 < 4; ++nt4) {
                const u32 off = swz8(wn + nt4 * 16 + bRow, kc);
                u32 x0, x1, x2, x3;
                ldsm_x4(x0, x1, x2, x3, base + AV_B + off);
                bb[nt4*2][0] = x0; bb[nt4*2][1] = x2;
                bb[nt4*2+1][0] = x1; bb[nt4*2+1][1] = x3;
            }
#pragma unroll
            for (int mt = 0; mt < 2; ++mt)
#pragma unroll
                for (int nt = 0; nt < 8; ++nt)
                    mma_f16(acc[mt][nt], ah[mt], bb[nt][0], bb[nt][1]);

            if (k16 == 0) {   // mid-stream refill, hidden under mma blocks
                const int sl = (s >= 1) ? s - 1 : 2;  // (kt+2)%3
                if (kt + 2 < KT) load_stage(kt + 2, sl);
                cp_commit();
            }
        }
        s = (s == 2) ? 0 : s + 1;
    }

    const int tq = lane >> 2;
    const int tr = (lane & 3) * 2;
#pragma unroll
    for (int mt = 0; mt < 2; ++mt) {
#pragma unroll
        for (int nt = 0; nt < 8; ++nt) {
            const int m = m0 + wm + mt * 16 + tq;
            const int n = n0 + wn + nt * 8 + tr;
            const float* a = acc[mt][nt];
            const long long b0 = (long long)bz * strideC + (long long)m * NPIX + n;
            const long long b1 = b0 + 8 * NPIX;
            *reinterpret_cast<float2*>(C + b0) = make_float2(a[0], a[1]);
            *reinterpret_cast<float2*>(C + b1) = make_float2(a[2], a[3]);
        }
    }
}

// ---------------- fused feature prep (both sides in one launch) --------------
__global__ __launch_bounds__(256)
void prep_features(const float* __restrict__ L, const float* __restrict__ R,
                   float* __restrict__ outL, float* __restrict__ outR,
                   u16* __restrict__ fL16p, u16* __restrict__ fR16p,
                   u16* __restrict__ hiL, u16* __restrict__ loL,
                   u16* __restrict__ hiR, u16* __restrict__ loR)
{
    __shared__ float tile[32][33];
    const int side = blockIdx.z >> 2, b = blockIdx.z & 3;
    const int n0 = blockIdx.x * 32;
    const int c0 = blockIdx.y * 32;
    const int tx = threadIdx.x, ty = threadIdx.y;  // 32 x 8

    const float* X = side ? R : L;
    float* outDst = side ? outR : outL;
    u16* f16 = side ? fR16p : fL16p;
    u16* hi = side ? hiR : hiL;
    u16* lo = side ? loR : loL;

    const float* src = X + ((long long)b * CIN + c0) * NPIX + n0;
#pragma unroll
    for (int r = 0; r < 32; r += 8) {
        const float v = src[(long long)(ty + r) * NPIX + tx];
        tile[ty + r][tx] = v;
        const long long cIdx = c0 + ty + r;
        outDst[((long long)b * 2 * CIN + cIdx) * NPIX + n0 + tx] = v;
        __half h = __float2half_rn(v);
        f16[((long long)b * CIN + cIdx) * NPIX + n0 + tx] = *reinterpret_cast<u16*>(&h);
    }
    __syncthreads();
#pragma unroll
    for (int r = 0; r < 32; r += 8) {
        float v = tile[tx][ty + r];
        u16 h, l; split2(v, h, l);
        long long o = ((long long)b * NPIX + n0 + ty + r) * CIN + c0 + tx;
        hi[o] = h; lo[o] = l;
    }
}

// merged weight prep: splits wq and wr into the concat arrays, plus bias concat.
__global__ __launch_bounds__(256)
void prep_weights(const float4* __restrict__ wq4, const float4* __restrict__ wr4,
                  uint2* __restrict__ hi, uint2* __restrict__ lo,
                  const float* __restrict__ bq, const float* __restrict__ br,
                  float* __restrict__ bdst)
{
    const long long nW4 = (long long)DHID * CIN / 4;   // per-weight uint2 count
    long long i = (long long)blockIdx.x * 256 + threadIdx.x;
    if (i < 2 * nW4) {
        const int second = i >= nW4;
        const long long j = second ? i - nW4 : i;
        float4 v = second ? wr4[j] : wq4[j];
        u16 h0,l0,h1,l1,h2,l2,h3,l3;
        split2(v.x,h0,l0); split2(v.y,h1,l1); split2(v.z,h2,l2); split2(v.w,h3,l3);
        hi[i] = make_uint2((u32)h0 | ((u32)h1 << 16), (u32)h2 | ((u32)h3 << 16));
        lo[i] = make_uint2((u32)l0 | ((u32)l1 << 16), (u32)l2 | ((u32)l3 << 16));
    }
    if (blockIdx.x == 0) {
        int t = threadIdx.x;
        bdst[t] = bq[t];
        bdst[t + 256] = br[t];
    }
}

// merged row softmax (both directions) fp32 -> attn fp16
__global__ __launch_bounds__(256)
void softmax_h(const float* __restrict__ S0p, const float* __restrict__ S1p,
               u16* __restrict__ A0p, u16* __restrict__ A1p)
{
    const int PER = NPIX / 256;  // 9
    const int total = BATCH * NPIX;
    const int dir = blockIdx.x >= total;
    const long long rb = (long long)(dir ? blockIdx.x - total : blockIdx.x) * NPIX;
    const float* p = (dir ? S1p : S0p) + rb;
    u16* A = (dir ? A1p : A0p);
    const int tid = threadIdx.x;

    float v[PER];
    float mx = -INFINITY;
#pragma unroll
    for (int i = 0; i < PER; ++i) { v[i] = p[tid + i*256]; mx = fmaxf(mx, v[i]); }

    __shared__ float red[8];
#pragma unroll
    for (int o = 16; o; o >>= 1) mx = fmaxf(mx, __shfl_xor_sync(0xffffffffu, mx, o));
    if ((tid & 31) == 0) red[tid >> 5] = mx;
    __syncthreads();
    mx = red[0];
#pragma unroll
    for (int i = 1; i < 8; ++i) mx = fmaxf(mx, red[i]);
    __syncthreads();

    float s = 0.f;
#pragma unroll
    for (int i = 0; i < PER; ++i) { v[i] = __expf(v[i] - mx); s += v[i]; }
#pragma unroll
    for (int o = 16; o; o >>= 1) s += __shfl_xor_sync(0xffffffffu, s, o);
    if ((tid & 31) == 0) red[tid >> 5] = s;
    __syncthreads();
    s = red[0];
#pragma unroll
    for (int i = 1; i < 8; ++i) s += red[i];

    const float inv = 1.f / s;
#pragma unroll
    for (int i = 0; i < PER; ++i) {
        __half h = __float2half_rn(v[i] * inv);
        A[rb + tid + i*256] = *reinterpret_cast<u16*>(&h);
    }
}

// ---------------- host --------------------------------------------------------
extern "C" void kernel_launch(void* const* d_in, const int* in_sizes, int n_in,
                              void* d_out, int out_size)
{
    const float* left  = (const float*)d_in[0];
    const float* right = (const float*)d_in[1];
    const float* wq    = (const float*)d_in[2];
    const float* bq    = (const float*)d_in[3];
    const float* wr    = (const float*)d_in[4];
    const float* br    = (const float*)d_in[5];
    float* out = (float*)d_out;

    void *fL16, *fR16, *fTLhi, *fTLlo, *fTRhi, *fTRlo;
    void *wqrhi, *wqrlo, *bqr;
    void *QLhi, *QLlo, *KRhi, *KRlo, *QRhi, *QRlo, *KLhi, *KLlo;
    void *S0, *S1, *A0, *A1;
    cudaGetSymbolAddress(&fL16, g_fL16);   cudaGetSymbolAddress(&fR16, g_fR16);
    cudaGetSymbolAddress(&fTLhi, g_fTLhi); cudaGetSymbolAddress(&fTLlo, g_fTLlo);
    cudaGetSymbolAddress(&fTRhi, g_fTRhi); cudaGetSymbolAddress(&fTRlo, g_fTRlo);
    cudaGetSymbolAddress(&wqrhi, g_wqrhi); cudaGetSymbolAddress(&wqrlo, g_wqrlo);
    cudaGetSymbolAddress(&bqr, g_bqr);
    cudaGetSymbolAddress(&QLhi, g_QLhi);   cudaGetSymbolAddress(&QLlo, g_QLlo);
    cudaGetSymbolAddress(&KRhi, g_KRhi);   cudaGetSymbolAddress(&KRlo, g_KRlo);
    cudaGetSymbolAddress(&QRhi, g_QRhi);   cudaGetSymbolAddress(&QRlo, g_QRlo);
    cudaGetSymbolAddress(&KLhi, g_KLhi);   cudaGetSymbolAddress(&KLlo, g_KLlo);
    cudaGetSymbolAddress(&S0, g_S0);       cudaGetSymbolAddress(&S1, g_S1);
    cudaGetSymbolAddress(&A0, g_A0);       cudaGetSymbolAddress(&A1, g_A1);

    cudaFuncSetAttribute(gemm_proj, cudaFuncAttributeMaxDynamicSharedMemorySize, GEMM_SMEM);
    cudaFuncSetAttribute(gemm_qk,   cudaFuncAttributeMaxDynamicSharedMemorySize, GEMM_SMEM);
    cudaFuncSetAttribute(gemm_av,   cudaFuncAttributeMaxDynamicSharedMemorySize, AV_SMEM);

    const long long outStride = 2LL * CIN * NPIX;
    float* outL = out;
    float* outR = out + (long long)BATCH * outStride;

    // ---- prep: weights + bias in one launch, fused feature prep ----
    {
        const long long nW4 = (long long)DHID * CIN / 4;
        prep_weights<<<(unsigned)((2 * nW4 + 255) / 256), 256>>>(
            (const float4*)wq, (const float4*)wr,
            (uint2*)wqrhi, (uint2*)wqrlo, bq, br, (float*)bqr);
        dim3 tg(NPIX / 32, CIN / 32, 2 * BATCH);
        prep_features<<<tg, dim3(32, 8)>>>(left, right, outL, outR,
            (u16*)fL16, (u16*)fR16,
            (u16*)fTLhi, (u16*)fTLlo, (u16*)fTRhi, (u16*)fTRlo);
    }

    // ---- merged projections (both features, one launch) ----
    {
        dim3 grid(2 * DHID / 128, NPIX / 128, 2 * BATCH);  // 4 x 18 x 8
        gemm_proj<<<grid, 256, GEMM_SMEM>>>(
            (const u16*)fTLhi, (const u16*)fTLlo, (const u16*)fTRhi, (const u16*)fTRlo,
            (const u16*)wqrhi, (const u16*)wqrlo, (const float*)bqr,
            (u16*)QLhi, (u16*)QLlo, (u16*)KLhi, (u16*)KLlo,
            (u16*)QRhi, (u16*)QRlo, (u16*)KRhi, (u16*)KRlo);
    }

    // ---- merged scores (both directions, one launch) ----
    {
        dim3 grid(NPIX / 128, NPIX / 128, 2 * BATCH);  // 18 x 18 x 8
        gemm_qk<<<grid, 256, GEMM_SMEM>>>(
            (const u16*)QLhi, (const u16*)QLlo, (const u16*)QRhi, (const u16*)QRlo,
            (const u16*)KRhi, (const u16*)KRlo, (const u16*)KLhi, (const u16*)KLlo,
            (float*)S0, (float*)S1);
    }

    // ---- merged softmax ----
    softmax_h<<<2 * BATCH * NPIX, 256>>>((const float*)S0, (const float*)S1,
                                         (u16*)A0, (u16*)A1);

    // ---- merged attn.V (both directions, one launch) ----
    {
        dim3 grid(NPIX / 128, CIN / 128, 2 * BATCH);   // 18 x 16 x 8
        gemm_av<<<grid, 256, AV_SMEM>>>(
            (const u16*)fR16, (const u16*)fL16, (const u16*)A0, (const u16*)A1,
            outL + (long long)CIN * NPIX, outR + (long long)CIN * NPIX);
    }
}